// round 12
// baseline (speedup 1.0000x reference)
#include <cuda_runtime.h>
#include <math.h>
#include <stdint.h>

#define BATCH 2048
#define DIN   512
#define DOUT  512
#define DINT  512
#define DNL   256

#define BAT_BLOCKS  168
#define GJ_BLOCKS   120
#define TOT_BLOCKS  288

// ---------------- device scratch ----------------
__device__ __align__(16) float g_WLU[512 * 1024];
__device__ __align__(16) float g_RPbuf[2][64 * 1024];  // deferred pivot-row commits
__device__ __align__(16) float g_a[BATCH * DNL];
__device__ __align__(16) float g_wm[BATCH * DNL];
__device__ __align__(16) float g_D11T[DNL * DNL];
__device__ __align__(16) float g_W1[DOUT * DNL];
__device__ __align__(16) float g_W2[DOUT * DIN];
__device__ __align__(16) float g_c1x0[DNL];
__device__ __align__(16) float g_fx0[DINT];
__device__ __align__(16) float g_ybias[DOUT];
__device__ volatile int g_bar_gj;
__device__ volatile int g_bar_bat;
__device__ volatile int g_done;
__device__ volatile int g_prep;
__device__ volatile int g_recdone;
__device__ int g_yctr;

__global__ void reset_kernel() {
    g_bar_gj = 0; g_bar_bat = 0; g_done = 0; g_prep = 0; g_recdone = 0; g_yctr = 0;
}

// ---------------- group barrier: RMW arrival, PLAIN-LOAD polling ----------------
__device__ __forceinline__ void gbar(volatile int* ctr, int nblocks, int& phase, int tid) {
    __syncthreads();
    ++phase;
    if (tid == 0) {
        __threadfence();
        atomicAdd((int*)ctr, 1);
        const int target = nblocks * phase;
        while (*ctr < target) __nanosleep(128);   // volatile LOAD: no L2-atomic serialization
        __threadfence();
    }
    __syncthreads();
}

__device__ __forceinline__ void wait_flag(volatile int* flag, int tid) {
    if (tid == 0) {
        while (*flag == 0) __nanosleep(128);      // volatile LOAD poll
    }
    __syncthreads();
    __threadfence();
}

// ---------------- register-resident 64x64 pivot inverse ----------------
__device__ __forceinline__ void invert_pivot(int pc, int tid, float* Ds,
                                             float* rowbuf, float* colbuf) {
    const int rg = tid >> 4, cg = tid & 15;
    float v[4][8];
#pragma unroll
    for (int i = 0; i < 4; ++i) {
        int r = rg * 4 + i;
#pragma unroll
        for (int j = 0; j < 8; ++j) {
            int c = cg * 8 + j;
            v[i][j] = (c < 64) ? g_WLU[(size_t)(pc + r) * 1024 + pc + c]
                               : ((c - 64) == r ? 1.f : 0.f);
        }
    }
    for (int jj = 0; jj < 64; ++jj) {
        if (rg == (jj >> 2)) {
#pragma unroll
            for (int i = 0; i < 4; ++i)
                if ((jj & 3) == i) {
#pragma unroll
                    for (int q = 0; q < 8; ++q) rowbuf[cg * 8 + q] = v[i][q];
                }
        }
        if (cg == (jj >> 3)) {
#pragma unroll
            for (int q = 0; q < 8; ++q)
                if ((jj & 7) == q) {
#pragma unroll
                    for (int i = 0; i < 4; ++i) colbuf[rg * 4 + i] = v[i][q];
                }
        }
        __syncthreads();
        const float pinv = 1.0f / rowbuf[jj];
        float f[4];
#pragma unroll
        for (int i = 0; i < 4; ++i) f[i] = colbuf[rg * 4 + i] * pinv;
        float rv[8];
#pragma unroll
        for (int q = 0; q < 8; ++q) rv[q] = rowbuf[cg * 8 + q];
#pragma unroll
        for (int i = 0; i < 4; ++i) {
            if (rg * 4 + i == jj) {
#pragma unroll
                for (int q = 0; q < 8; ++q) v[i][q] = rv[q] * pinv;
            } else {
#pragma unroll
                for (int q = 0; q < 8; ++q) v[i][q] -= f[i] * rv[q];
            }
        }
        __syncthreads();
    }
#pragma unroll
    for (int i = 0; i < 4; ++i) {
        int r = rg * 4 + i;
#pragma unroll
        for (int j = 0; j < 8; ++j) {
            int c = cg * 8 + j;
            if (c >= 64) Ds[r * 65 + (c - 64)] = v[i][j];
        }
    }
    __syncthreads();
}

// ---------------- TN tile ----------------
__device__ void tn_tile(float* __restrict__ C,
                        const float* __restrict__ A, int lda,
                        const float* __restrict__ B, int ldb,
                        const float* __restrict__ Add, int N, int K,
                        int m0, int n0, int tid, float* smem) {
    float* As = smem;
    float* Bs = smem + 16 * 68;
    const int tr = tid >> 4, tc = tid & 15;
    float acc[4][4] = {};
    for (int t0 = 0; t0 < K; t0 += 16) {
        __syncthreads();
        for (int idx = tid; idx < 1024; idx += 256) {
            int t = idx >> 6, m = idx & 63;
            As[t * 68 + m] = A[(size_t)(t0 + t) * lda + m0 + m];
            Bs[t * 68 + m] = B[(size_t)(t0 + t) * ldb + n0 + m];
        }
        __syncthreads();
#pragma unroll
        for (int t = 0; t < 16; ++t) {
            float a[4], bv[4];
#pragma unroll
            for (int i = 0; i < 4; ++i) a[i] = As[t * 68 + tr * 4 + i];
#pragma unroll
            for (int j = 0; j < 4; ++j) bv[j] = Bs[t * 68 + tc * 4 + j];
#pragma unroll
            for (int i = 0; i < 4; ++i)
#pragma unroll
                for (int j = 0; j < 4; ++j) acc[i][j] += a[i] * bv[j];
        }
    }
    __syncthreads();
#pragma unroll
    for (int i = 0; i < 4; ++i) {
        int r = m0 + tr * 4 + i;
#pragma unroll
        for (int j = 0; j < 4; ++j) {
            float v = acc[i][j];
            if (Add) v += Add[(size_t)r * N + n0 + tc * 4 + j];
            C[(size_t)r * N + n0 + tc * 4 + j] = v;
        }
    }
}

// ---------------- 3xTF32 MMA GEMM machinery ----------------
__device__ __forceinline__ uint32_t f2tf(float f) {
    uint32_t u;
    asm("cvt.rna.tf32.f32 %0, %1;" : "=r"(u) : "f"(f));
    return u;
}
__device__ __forceinline__ void mma8(float& c0, float& c1, float& c2, float& c3,
                                     uint32_t a0, uint32_t a1, uint32_t a2, uint32_t a3,
                                     uint32_t b0, uint32_t b1) {
    asm volatile(
        "mma.sync.aligned.m16n8k8.row.col.f32.tf32.tf32.f32 "
        "{%0,%1,%2,%3},{%4,%5,%6,%7},{%8,%9},{%0,%1,%2,%3};"
        : "+f"(c0), "+f"(c1), "+f"(c2), "+f"(c3)
        : "r"(a0), "r"(a1), "r"(a2), "r"(a3), "r"(b0), "r"(b1));
}

#define ASTRIDE 20
#define ABUF (128 * ASTRIDE)
#define BBUF (64 * ASTRIDE)
#define GEMM_SMEM ((2 * ABUF + 2 * BBUF) * 8)  // 61440 bytes

__device__ __forceinline__ void stage_store(uint32_t* Ah, uint32_t* Al,
                                            uint32_t* Bh, uint32_t* Bl,
                                            int arow, int akq, int brow, int bkq,
                                            float4 ra0, float4 ra1, float4 rb0) {
    uint32_t* ah = Ah + arow * ASTRIDE + akq;
    uint32_t* al = Al + arow * ASTRIDE + akq;
    float av[8] = {ra0.x, ra0.y, ra0.z, ra0.w, ra1.x, ra1.y, ra1.z, ra1.w};
#pragma unroll
    for (int j = 0; j < 8; ++j) {
        uint32_t h = f2tf(av[j]);
        ah[j] = h;
        al[j] = f2tf(av[j] - __uint_as_float(h));
    }
    uint32_t* bh = Bh + brow * ASTRIDE + bkq;
    uint32_t* bl = Bl + brow * ASTRIDE + bkq;
    float bv[4] = {rb0.x, rb0.y, rb0.z, rb0.w};
#pragma unroll
    for (int j = 0; j < 4; ++j) {
        uint32_t h = f2tf(bv[j]);
        bh[j] = h;
        bl[j] = f2tf(bv[j] - __uint_as_float(h));
    }
}

__device__ void gemm_part(const float* __restrict__ A,
                          const float* __restrict__ Bm,
                          int K, int ldb, int m0, int n0, int tid,
                          uint32_t* Ah, uint32_t* Al,
                          uint32_t* Bh, uint32_t* Bl,
                          float (&acc)[2][4][4]) {
    const int arow = tid >> 1, akq = (tid & 1) * 8;
    const int brow = tid >> 2, bkq = (tid & 3) * 4;
    const int lane = tid & 31, warp = tid >> 5;
    const int wm = warp >> 1, wn = warp & 1, g = lane >> 2, tg = lane & 3;
    const int nt = K >> 4;
    float4 ra0, ra1, rb0;
    {
        const float* ap = A + (size_t)(m0 + arow) * K + akq;
        ra0 = *(const float4*)ap;
        ra1 = *(const float4*)(ap + 4);
        const float* bp = Bm + (size_t)(n0 + brow) * ldb + bkq;
        rb0 = *(const float4*)bp;
    }
    __syncthreads();
    stage_store(Ah, Al, Bh, Bl, arow, akq, brow, bkq, ra0, ra1, rb0);
    __syncthreads();
    for (int t = 0; t < nt; ++t) {
        const int c = t & 1;
        if (t + 1 < nt) {
            const float* ap = A + (size_t)(m0 + arow) * K + (t + 1) * 16 + akq;
            ra0 = *(const float4*)ap;
            ra1 = *(const float4*)(ap + 4);
            const float* bp = Bm + (size_t)(n0 + brow) * ldb + (t + 1) * 16 + bkq;
            rb0 = *(const float4*)bp;
        }
        const uint32_t* Abh = Ah + c * ABUF;
        const uint32_t* Abl = Al + c * ABUF;
        const uint32_t* Bbh = Bh + c * BBUF;
        const uint32_t* Bbl = Bl + c * BBUF;
#pragma unroll
        for (int ks = 0; ks < 16; ks += 8) {
            uint32_t ah[2][4], al[2][4], bh[4][2], bl[4][2];
#pragma unroll
            for (int i = 0; i < 2; ++i) {
                int r = (wm * 32 + i * 16 + g) * ASTRIDE + ks + tg;
                ah[i][0] = Abh[r];                   al[i][0] = Abl[r];
                ah[i][1] = Abh[r + 8 * ASTRIDE];     al[i][1] = Abl[r + 8 * ASTRIDE];
                ah[i][2] = Abh[r + 4];               al[i][2] = Abl[r + 4];
                ah[i][3] = Abh[r + 8 * ASTRIDE + 4]; al[i][3] = Abl[r + 8 * ASTRIDE + 4];
            }
#pragma unroll
            for (int j = 0; j < 4; ++j) {
                int r = (wn * 32 + j * 8 + g) * ASTRIDE + ks + tg;
                bh[j][0] = Bbh[r];     bl[j][0] = Bbl[r];
                bh[j][1] = Bbh[r + 4]; bl[j][1] = Bbl[r + 4];
            }
#pragma unroll
            for (int i = 0; i < 2; ++i)
#pragma unroll
                for (int j = 0; j < 4; ++j) {
                    mma8(acc[i][j][0], acc[i][j][1], acc[i][j][2], acc[i][j][3],
                         al[i][0], al[i][1], al[i][2], al[i][3], bh[j][0], bh[j][1]);
                    mma8(acc[i][j][0], acc[i][j][1], acc[i][j][2], acc[i][j][3],
                         ah[i][0], ah[i][1], ah[i][2], ah[i][3], bl[j][0], bl[j][1]);
                    mma8(acc[i][j][0], acc[i][j][1], acc[i][j][2], acc[i][j][3],
                         ah[i][0], ah[i][1], ah[i][2], ah[i][3], bh[j][0], bh[j][1]);
                }
        }
        __syncthreads();
        if (t + 1 < nt) {
            stage_store(Ah + (1 - c) * ABUF, Al + (1 - c) * ABUF,
                        Bh + (1 - c) * BBUF, Bl + (1 - c) * BBUF,
                        arow, akq, brow, bkq, ra0, ra1, rb0);
            __syncthreads();
        }
    }
}

__device__ void gemm_tile(float* __restrict__ C, int N, const float* __restrict__ bias,
                          const float* A0, const float* B0, int K0, int l0,
                          const float* A1, const float* B1, int K1, int l1,
                          int m0, int n0, int tid, uint32_t* sm_u) {
    uint32_t* Ah = sm_u;
    uint32_t* Bh = Ah + 2 * ABUF;
    uint32_t* Al = Bh + 2 * BBUF;
    uint32_t* Bl = Al + 2 * ABUF;
    float acc[2][4][4];
#pragma unroll
    for (int i = 0; i < 2; ++i)
#pragma unroll
        for (int j = 0; j < 4; ++j)
#pragma unroll
            for (int q = 0; q < 4; ++q) acc[i][j][q] = 0.f;

    gemm_part(A0, B0, K0, l0, m0, n0, tid, Ah, Al, Bh, Bl, acc);
    if (A1) gemm_part(A1, B1, K1, l1, m0, n0, tid, Ah, Al, Bh, Bl, acc);

    const int lane = tid & 31, warp = tid >> 5;
    const int wm = warp >> 1, wn = warp & 1, g = lane >> 2, tg = lane & 3;
#pragma unroll
    for (int i = 0; i < 2; ++i)
#pragma unroll
        for (int j = 0; j < 4; ++j) {
            int r = m0 + wm * 32 + i * 16 + g;
            int cc = n0 + wn * 32 + j * 8 + 2 * tg;
            float2 bb = make_float2(0.f, 0.f);
            if (bias) bb = *(const float2*)&bias[cc];
            *(float2*)&C[(size_t)r * N + cc] =
                make_float2(acc[i][j][0] + bb.x, acc[i][j][1] + bb.y);
            *(float2*)&C[(size_t)(r + 8) * N + cc] =
                make_float2(acc[i][j][2] + bb.x, acc[i][j][3] + bb.y);
        }
}

// =====================================================================
// MEGA KERNEL v3: identical to v2 except all spin-polls are volatile
// LOADS (no L2-atomic RMW serialization on the hot counters).
// =====================================================================
__global__ void __launch_bounds__(256, 2) mega_kernel(
    const float* __restrict__ u, const float* __restrict__ x0,
    const float* __restrict__ C1, const float* __restrict__ D11,
    const float* __restrict__ D12, const float* __restrict__ lam,
    const float* __restrict__ Fm, const float* __restrict__ B1,
    const float* __restrict__ B2, const float* __restrict__ E,
    const float* __restrict__ C2, const float* __restrict__ D22,
    float* __restrict__ yout) {
    extern __shared__ float smf[];
    __shared__ int s_tile;
    const int b = blockIdx.x;
    const int tid = threadIdx.x;
    int phase = 0;

    if (b >= BAT_BLOCKS) {
        // ================= GJ GROUP (120 blocks) =================
        const int g = b - BAT_BLOCKS;  // 0..119
        float* Ds = smf;
        float* RP = Ds + 64 * 65;
        float* Fs = RP + 64 * 65;
        float* rowbuf = Fs + 64 * 65;
        float* colbuf = rowbuf + 128;
        const int tr = tid >> 4, tc = tid & 15;

        // --- transposed init: WLU = [E^T | C2^T] ---
        {
            float* tsh = smf;
            const int tx = tid & 31, ty = tid >> 5;
            for (int tu = g; tu < 512; tu += GJ_BLOCKS) {
                const int R0 = (tu & 15) * 32;
                const int Cc0 = (tu >> 4) * 32;
                const float* src = (Cc0 < 512) ? (E + (size_t)Cc0 * 512 + R0)
                                               : (C2 + (size_t)(Cc0 - 512) * 512 + R0);
                __syncthreads();
#pragma unroll
                for (int i = 0; i < 32; i += 8)
                    tsh[(ty + i) * 33 + tx] = src[(size_t)(ty + i) * 512 + tx];
                __syncthreads();
#pragma unroll
                for (int i = 0; i < 32; i += 8)
                    g_WLU[(size_t)(R0 + ty + i) * 1024 + Cc0 + tx] = tsh[tx * 33 + ty + i];
            }
        }
        gbar(&g_bar_gj, GJ_BLOCKS, phase, tid);

        // --- 8 GJ steps, 1 barrier each ---
        for (int kb = 0; kb < 8; ++kb) {
            const int pc = kb * 64;
            const int ntiles = 15 - kb;
            const int tile = g >> 3, chunk = g & 7;
            const bool active = (tile < ntiles);

            if (active) {
                const int c0 = pc + 64 + tile * 64;
                invert_pivot(pc, tid, Ds, rowbuf, colbuf);

                for (int idx = tid; idx < 4096; idx += 256) {
                    int k = idx >> 6, c = idx & 63;
                    Fs[k * 65 + c] = g_WLU[(size_t)(pc + k) * 1024 + c0 + c];
                }
                __syncthreads();

                float rp[4][4] = {};
                for (int k = 0; k < 64; ++k) {
                    float w0 = Fs[k * 65 + tc * 4 + 0];
                    float w1 = Fs[k * 65 + tc * 4 + 1];
                    float w2 = Fs[k * 65 + tc * 4 + 2];
                    float w3 = Fs[k * 65 + tc * 4 + 3];
#pragma unroll
                    for (int i = 0; i < 4; ++i) {
                        float d = Ds[(tr * 4 + i) * 65 + k];
                        rp[i][0] += d * w0; rp[i][1] += d * w1;
                        rp[i][2] += d * w2; rp[i][3] += d * w3;
                    }
                }
                __syncthreads();
#pragma unroll
                for (int i = 0; i < 4; ++i)
#pragma unroll
                    for (int j = 0; j < 4; ++j)
                        RP[(tr * 4 + i) * 65 + tc * 4 + j] = rp[i][j];
                __syncthreads();

                if (chunk == kb) {
                    float* dst = &g_RPbuf[kb & 1][0];
                    for (int idx = tid; idx < 4096; idx += 256) {
                        int r = idx >> 6, c = idx & 63;
                        dst[(size_t)r * 1024 + c0 + c] = RP[r * 65 + c];
                    }
                } else {
                    const int r0 = chunk * 64;
                    const bool prev = (kb > 0) && (chunk == kb - 1);
                    const float* pbuf = &g_RPbuf[(kb + 1) & 1][0];
                    for (int idx = tid; idx < 4096; idx += 256) {
                        int r = idx >> 6, k = idx & 63;
                        Fs[r * 65 + k] = prev ? pbuf[(size_t)r * 1024 + pc + k]
                                              : g_WLU[(size_t)(r0 + r) * 1024 + pc + k];
                    }
                    __syncthreads();
                    float acc[4][4] = {};
                    for (int k = 0; k < 64; ++k) {
                        float w0 = RP[k * 65 + tc * 4 + 0];
                        float w1 = RP[k * 65 + tc * 4 + 1];
                        float w2 = RP[k * 65 + tc * 4 + 2];
                        float w3 = RP[k * 65 + tc * 4 + 3];
#pragma unroll
                        for (int i = 0; i < 4; ++i) {
                            float f = Fs[(tr * 4 + i) * 65 + k];
                            acc[i][0] += f * w0; acc[i][1] += f * w1;
                            acc[i][2] += f * w2; acc[i][3] += f * w3;
                        }
                    }
#pragma unroll
                    for (int i = 0; i < 4; ++i) {
                        const size_t off = (size_t)(r0 + tr * 4 + i) * 1024 + c0 + tc * 4;
                        float4 o = prev ? *(const float4*)&pbuf[(size_t)(tr * 4 + i) * 1024 + c0 + tc * 4]
                                        : *(const float4*)&g_WLU[off];
                        o.x -= acc[i][0]; o.y -= acc[i][1];
                        o.z -= acc[i][2]; o.w -= acc[i][3];
                        *(float4*)&g_WLU[off] = o;
                    }
                }
            }
            gbar(&g_bar_gj, GJ_BLOCKS, phase, tid);
        }

        // --- final commit of chunk-7 pivot rows (cols 512..1024) ---
        {
            const float* src = &g_RPbuf[1][0];
            for (int t = g * 256 + tid; t < 8192; t += GJ_BLOCKS * 256) {
                int r = t >> 7, c4 = (t & 127) * 4;
                *(float4*)&g_WLU[(size_t)(448 + r) * 1024 + 512 + c4] =
                    *(const float4*)&src[(size_t)r * 1024 + 512 + c4];
            }
        }
        gbar(&g_bar_gj, GJ_BLOCKS, phase, tid);

        // --- fold: W1 (32), W2 (64), ybias (2) = 98 units ---
        const float* G = &g_WLU[512];
        for (int fu = g; fu < 98; fu += GJ_BLOCKS) {
            if (fu < 32) {
                tn_tile(g_W1, G, 1024, B1, 256, nullptr, 256, 512,
                        (fu >> 2) * 64, (fu & 3) * 64, tid, smf);
            } else if (fu < 96) {
                int q = fu - 32;
                tn_tile(g_W2, G, 1024, B2, 512, D22, 512, 512,
                        (q >> 3) * 64, (q & 7) * 64, tid, smf);
            } else {
                wait_flag(&g_prep, tid);
                float* xs = smf;
                for (int i = tid; i < 512; i += 256) xs[i] = g_fx0[i];
                __syncthreads();
                int n = (fu - 96) * 256 + tid;
                float sv = 0.f;
#pragma unroll 8
                for (int t = 0; t < 512; ++t) sv += G[(size_t)t * 1024 + n] * xs[t];
                g_ybias[n] = sv;
                __syncthreads();
            }
        }
        gbar(&g_bar_gj, GJ_BLOCKS, phase, tid);
        if (g == 0 && tid == 0) {
            __threadfence();
            atomicExch((int*)&g_done, 1);
        }

        wait_flag(&g_recdone, tid);
    } else {
        // ================= BATCH GROUP (168 blocks) =================
        const int v = b;

        if (v < 67) {
            if (v < 64) {
                float* tsh = smf;
                const int bx = (v & 7) * 32, by = (v >> 3) * 32;
                const int tx = tid & 31, ty = tid >> 5;
#pragma unroll
                for (int i = 0; i < 32; i += 8)
                    tsh[(ty + i) * 33 + tx] = D11[(size_t)(by + ty + i) * 256 + bx + tx];
                __syncthreads();
#pragma unroll
                for (int i = 0; i < 32; i += 8)
                    g_D11T[(size_t)(bx + ty + i) * 256 + by + tx] = tsh[tx * 33 + ty + i];
            } else {
                const float4* xv = (const float4*)x0;
                if (v == 64) {
                    int n = tid;
                    const float4* r = (const float4*)(C1 + (size_t)n * DIN);
                    float s = 0.f;
                    for (int k = 0; k < DIN / 4; ++k) {
                        float4 a = r[k], bb = xv[k];
                        s += a.x * bb.x + a.y * bb.y + a.z * bb.z + a.w * bb.w;
                    }
                    g_c1x0[n] = s;
                } else {
                    int n = (v - 65) * 256 + tid;
                    const float4* r = (const float4*)(Fm + (size_t)n * DINT);
                    float s = 0.f;
                    for (int k = 0; k < DINT / 4; ++k) {
                        float4 a = r[k], bb = xv[k];
                        s += a.x * bb.x + a.y * bb.y + a.z * bb.z + a.w * bb.w;
                    }
                    g_fx0[n] = s;
                }
            }
        }
        gbar(&g_bar_bat, BAT_BLOCKS, phase, tid);
        if (v == 0 && tid == 0) {
            __threadfence();
            atomicExch((int*)&g_prep, 1);
        }

        if (v < 64) {
            gemm_tile(g_a, 256, g_c1x0,
                      u, D12, 512, 512,
                      nullptr, nullptr, 0, 0,
                      (v >> 2) * 128, (v & 3) * 64, tid, (uint32_t*)smf);
        }
        gbar(&g_bar_bat, BAT_BLOCKS, phase, tid);

        for (int ru = v; ru < 256; ru += BAT_BLOCKS) {
            const int lane = tid & 31;
            const int rb = ru * 8 + (tid >> 5);
            const float* arow = g_a + (size_t)rb * 256;
            float acc[8], linv[8], wv[8];
#pragma unroll
            for (int q = 0; q < 8; ++q) {
                acc[q] = arow[q * 32 + lane];
                linv[q] = 1.0f / lam[q * 32 + lane];
            }
#pragma unroll
            for (int q = 0; q < 8; ++q) {
#pragma unroll 8
                for (int t = 0; t < 32; ++t) {
                    int s = q * 32 + t;
                    float scaled = acc[q] * linv[q];
                    float vx = __shfl_sync(0xffffffffu, scaled, t);
                    float wt = tanhf(vx);
                    if (lane == t) wv[q] = wt;
                    const float* col = g_D11T + (size_t)s * 256;
                    if (lane > t) acc[q] += col[q * 32 + lane] * wt;
#pragma unroll
                    for (int q2 = q + 1; q2 < 8; ++q2)
                        acc[q2] += col[q2 * 32 + lane] * wt;
                }
            }
#pragma unroll
            for (int q = 0; q < 8; ++q)
                g_wm[(size_t)rb * 256 + q * 32 + lane] = wv[q];
        }
        gbar(&g_bar_bat, BAT_BLOCKS, phase, tid);
        if (v == 0 && tid == 0) {
            __threadfence();
            atomicExch((int*)&g_recdone, 1);
        }

        wait_flag(&g_done, tid);
    }

    // ============ shared y-GEMM work queue (all 288 blocks) ============
    for (;;) {
        __syncthreads();
        if (tid == 0) s_tile = atomicAdd(&g_yctr, 1);
        __syncthreads();
        const int t = s_tile;
        if (t >= 128) break;
        gemm_tile(yout, 512, g_ybias,
                  g_wm, g_W1, 256, 256,
                  u, g_W2, 512, 512,
                  (t >> 3) * 128, (t & 7) * 64, tid, (uint32_t*)smf);
    }
}

// ---------------- launch ----------------
extern "C" void kernel_launch(void* const* d_in, const int* in_sizes, int n_in,
                              void* d_out, int out_size) {
    const float *u, *x0, *C1, *D11, *D12, *lam, *Fm, *B1, *B2, *E, *C2, *D21, *D22;
    if (in_sizes[0] == BATCH * DIN) {
        u   = (const float*)d_in[0];  x0  = (const float*)d_in[1];
        C1  = (const float*)d_in[2];  D11 = (const float*)d_in[3];
        D12 = (const float*)d_in[4];  lam = (const float*)d_in[5];
        Fm  = (const float*)d_in[6];  B1  = (const float*)d_in[7];
        B2  = (const float*)d_in[8];  E   = (const float*)d_in[9];
        C2  = (const float*)d_in[10]; D21 = (const float*)d_in[11];
        D22 = (const float*)d_in[12];
    } else {
        C1  = (const float*)d_in[0];  D11 = (const float*)d_in[1];
        D12 = (const float*)d_in[2];  lam = (const float*)d_in[3];
        Fm  = (const float*)d_in[4];  B1  = (const float*)d_in[5];
        B2  = (const float*)d_in[6];  E   = (const float*)d_in[7];
        C2  = (const float*)d_in[8];  D21 = (const float*)d_in[9];
        D22 = (const float*)d_in[10]; u   = (const float*)d_in[11];
        x0  = (const float*)d_in[12];
    }
    (void)D21;  // identically zero by construction

    cudaFuncSetAttribute(mega_kernel,
                         cudaFuncAttributeMaxDynamicSharedMemorySize, GEMM_SMEM);

    reset_kernel<<<1, 32>>>();
    mega_kernel<<<TOT_BLOCKS, 256, GEMM_SMEM>>>(
        u, x0, C1, D11, D12, lam, Fm, B1, B2, E, C2, D22, (float*)d_out);
}

// round 13
// speedup vs baseline: 1.8326x; 1.8326x over previous
#include <cuda_runtime.h>
#include <math.h>
#include <stdint.h>

#define BATCH 2048
#define DIN   512
#define DOUT  512
#define DINT  512
#define DNL   256

#define BAT_BLOCKS  168
#define GJ_BLOCKS   120
#define TOT_BLOCKS  288

// ---------------- device scratch ----------------
__device__ __align__(16) float g_WLU[512 * 1024];
__device__ __align__(16) float g_RPbuf[2][64 * 1024];  // deferred pivot-row commits
__device__ __align__(16) float g_a[BATCH * DNL];
__device__ __align__(16) float g_wm[BATCH * DNL];
__device__ __align__(16) float g_D11T[DNL * DNL];
__device__ __align__(16) float g_W1[DOUT * DNL];
__device__ __align__(16) float g_W2[DOUT * DIN];
__device__ __align__(16) float g_c1x0[DNL];
__device__ __align__(16) float g_fx0[DINT];
__device__ __align__(16) float g_ybias[DOUT];
__device__ volatile int g_bar_gj;
__device__ volatile int g_bar_bat;
__device__ volatile int g_done;
__device__ volatile int g_prep;
__device__ volatile int g_recdone;
__device__ int g_yctr;

__global__ void reset_kernel() {
    g_bar_gj = 0; g_bar_bat = 0; g_done = 0; g_prep = 0; g_recdone = 0; g_yctr = 0;
}

// ---------------- group barrier: RMW arrival, plain-load polling ----------------
__device__ __forceinline__ void gbar(volatile int* ctr, int nblocks, int& phase, int tid) {
    __syncthreads();
    ++phase;
    if (tid == 0) {
        __threadfence();
        atomicAdd((int*)ctr, 1);
        const int target = nblocks * phase;
        while (*ctr < target) __nanosleep(128);
        __threadfence();
    }
    __syncthreads();
}

__device__ __forceinline__ void wait_flag(volatile int* flag, int tid) {
    if (tid == 0) {
        while (*flag == 0) __nanosleep(128);
    }
    __syncthreads();
    __threadfence();
}

// ---------------- register-resident 64x64 pivot inverse ----------------
// FULLY UNROLLED jj loop: all register indices static, publishes are direct
// stores by the owning threads (no predicated-store storm, no spill pressure).
__device__ __forceinline__ void invert_pivot(int pc, int tid, float* Ds,
                                             float* rowbuf, float* colbuf) {
    const int rg = tid >> 4, cg = tid & 15;
    float v[4][8];
#pragma unroll
    for (int i = 0; i < 4; ++i) {
        int r = rg * 4 + i;
#pragma unroll
        for (int j = 0; j < 8; ++j) {
            int c = cg * 8 + j;
            v[i][j] = (c < 64) ? g_WLU[(size_t)(pc + r) * 1024 + pc + c]
                               : ((c - 64) == r ? 1.f : 0.f);
        }
    }
#pragma unroll 64
    for (int jj = 0; jj < 64; ++jj) {
        const int pr = jj >> 2, sub = jj & 3;       // compile-time after unroll
        const int pcg = jj >> 3, subc = jj & 7;
        if (rg == pr) {
#pragma unroll
            for (int q = 0; q < 8; ++q) rowbuf[cg * 8 + q] = v[sub][q];
        }
        if (cg == pcg) {
#pragma unroll
            for (int i = 0; i < 4; ++i) colbuf[rg * 4 + i] = v[i][subc];
        }
        __syncthreads();
        const float pinv = 1.0f / rowbuf[jj];
        float f[4];
#pragma unroll
        for (int i = 0; i < 4; ++i) f[i] = colbuf[rg * 4 + i] * pinv;
        float rv[8];
#pragma unroll
        for (int q = 0; q < 8; ++q) rv[q] = rowbuf[cg * 8 + q];
        if (rg == pr) {
#pragma unroll
            for (int q = 0; q < 8; ++q) v[sub][q] = rv[q] * pinv;
        }
#pragma unroll
        for (int i = 0; i < 4; ++i) {
            if (rg == pr && i == sub) continue;     // compile-time prune
#pragma unroll
            for (int q = 0; q < 8; ++q) v[i][q] -= f[i] * rv[q];
        }
        __syncthreads();
    }
#pragma unroll
    for (int i = 0; i < 4; ++i) {
        int r = rg * 4 + i;
#pragma unroll
        for (int j = 0; j < 8; ++j) {
            int c = cg * 8 + j;
            if (c >= 64) Ds[r * 65 + (c - 64)] = v[i][j];
        }
    }
    __syncthreads();
}

// ---------------- TN tile ----------------
__device__ void tn_tile(float* __restrict__ C,
                        const float* __restrict__ A, int lda,
                        const float* __restrict__ B, int ldb,
                        const float* __restrict__ Add, int N, int K,
                        int m0, int n0, int tid, float* smem) {
    float* As = smem;
    float* Bs = smem + 16 * 68;
    const int tr = tid >> 4, tc = tid & 15;
    float acc[4][4] = {};
    for (int t0 = 0; t0 < K; t0 += 16) {
        __syncthreads();
        for (int idx = tid; idx < 1024; idx += 256) {
            int t = idx >> 6, m = idx & 63;
            As[t * 68 + m] = A[(size_t)(t0 + t) * lda + m0 + m];
            Bs[t * 68 + m] = B[(size_t)(t0 + t) * ldb + n0 + m];
        }
        __syncthreads();
#pragma unroll
        for (int t = 0; t < 16; ++t) {
            float a[4], bv[4];
#pragma unroll
            for (int i = 0; i < 4; ++i) a[i] = As[t * 68 + tr * 4 + i];
#pragma unroll
            for (int j = 0; j < 4; ++j) bv[j] = Bs[t * 68 + tc * 4 + j];
#pragma unroll
            for (int i = 0; i < 4; ++i)
#pragma unroll
                for (int j = 0; j < 4; ++j) acc[i][j] += a[i] * bv[j];
        }
    }
    __syncthreads();
#pragma unroll
    for (int i = 0; i < 4; ++i) {
        int r = m0 + tr * 4 + i;
#pragma unroll
        for (int j = 0; j < 4; ++j) {
            float v = acc[i][j];
            if (Add) v += Add[(size_t)r * N + n0 + tc * 4 + j];
            C[(size_t)r * N + n0 + tc * 4 + j] = v;
        }
    }
}

// ---------------- 3xTF32 MMA GEMM machinery ----------------
__device__ __forceinline__ uint32_t f2tf(float f) {
    uint32_t u;
    asm("cvt.rna.tf32.f32 %0, %1;" : "=r"(u) : "f"(f));
    return u;
}
__device__ __forceinline__ void mma8(float& c0, float& c1, float& c2, float& c3,
                                     uint32_t a0, uint32_t a1, uint32_t a2, uint32_t a3,
                                     uint32_t b0, uint32_t b1) {
    asm volatile(
        "mma.sync.aligned.m16n8k8.row.col.f32.tf32.tf32.f32 "
        "{%0,%1,%2,%3},{%4,%5,%6,%7},{%8,%9},{%0,%1,%2,%3};"
        : "+f"(c0), "+f"(c1), "+f"(c2), "+f"(c3)
        : "r"(a0), "r"(a1), "r"(a2), "r"(a3), "r"(b0), "r"(b1));
}

#define ASTRIDE 20
#define ABUF (128 * ASTRIDE)
#define BBUF (64 * ASTRIDE)
#define GEMM_SMEM ((2 * ABUF + 2 * BBUF) * 8)  // 61440 bytes

__device__ __forceinline__ void stage_store(uint32_t* Ah, uint32_t* Al,
                                            uint32_t* Bh, uint32_t* Bl,
                                            int arow, int akq, int brow, int bkq,
                                            float4 ra0, float4 ra1, float4 rb0) {
    uint32_t* ah = Ah + arow * ASTRIDE + akq;
    uint32_t* al = Al + arow * ASTRIDE + akq;
    float av[8] = {ra0.x, ra0.y, ra0.z, ra0.w, ra1.x, ra1.y, ra1.z, ra1.w};
#pragma unroll
    for (int j = 0; j < 8; ++j) {
        uint32_t h = f2tf(av[j]);
        ah[j] = h;
        al[j] = f2tf(av[j] - __uint_as_float(h));
    }
    uint32_t* bh = Bh + brow * ASTRIDE + bkq;
    uint32_t* bl = Bl + brow * ASTRIDE + bkq;
    float bv[4] = {rb0.x, rb0.y, rb0.z, rb0.w};
#pragma unroll
    for (int j = 0; j < 4; ++j) {
        uint32_t h = f2tf(bv[j]);
        bh[j] = h;
        bl[j] = f2tf(bv[j] - __uint_as_float(h));
    }
}

__device__ void gemm_part(const float* __restrict__ A,
                          const float* __restrict__ Bm,
                          int K, int ldb, int m0, int n0, int tid,
                          uint32_t* Ah, uint32_t* Al,
                          uint32_t* Bh, uint32_t* Bl,
                          float (&acc)[2][4][4]) {
    const int arow = tid >> 1, akq = (tid & 1) * 8;
    const int brow = tid >> 2, bkq = (tid & 3) * 4;
    const int lane = tid & 31, warp = tid >> 5;
    const int wm = warp >> 1, wn = warp & 1, g = lane >> 2, tg = lane & 3;
    const int nt = K >> 4;
    float4 ra0, ra1, rb0;
    {
        const float* ap = A + (size_t)(m0 + arow) * K + akq;
        ra0 = *(const float4*)ap;
        ra1 = *(const float4*)(ap + 4);
        const float* bp = Bm + (size_t)(n0 + brow) * ldb + bkq;
        rb0 = *(const float4*)bp;
    }
    __syncthreads();
    stage_store(Ah, Al, Bh, Bl, arow, akq, brow, bkq, ra0, ra1, rb0);
    __syncthreads();
    for (int t = 0; t < nt; ++t) {
        const int c = t & 1;
        if (t + 1 < nt) {
            const float* ap = A + (size_t)(m0 + arow) * K + (t + 1) * 16 + akq;
            ra0 = *(const float4*)ap;
            ra1 = *(const float4*)(ap + 4);
            const float* bp = Bm + (size_t)(n0 + brow) * ldb + (t + 1) * 16 + bkq;
            rb0 = *(const float4*)bp;
        }
        const uint32_t* Abh = Ah + c * ABUF;
        const uint32_t* Abl = Al + c * ABUF;
        const uint32_t* Bbh = Bh + c * BBUF;
        const uint32_t* Bbl = Bl + c * BBUF;
#pragma unroll
        for (int ks = 0; ks < 16; ks += 8) {
            uint32_t ah[2][4], al[2][4], bh[4][2], bl[4][2];
#pragma unroll
            for (int i = 0; i < 2; ++i) {
                int r = (wm * 32 + i * 16 + g) * ASTRIDE + ks + tg;
                ah[i][0] = Abh[r];                   al[i][0] = Abl[r];
                ah[i][1] = Abh[r + 8 * ASTRIDE];     al[i][1] = Abl[r + 8 * ASTRIDE];
                ah[i][2] = Abh[r + 4];               al[i][2] = Abl[r + 4];
                ah[i][3] = Abh[r + 8 * ASTRIDE + 4]; al[i][3] = Abl[r + 8 * ASTRIDE + 4];
            }
#pragma unroll
            for (int j = 0; j < 4; ++j) {
                int r = (wn * 32 + j * 8 + g) * ASTRIDE + ks + tg;
                bh[j][0] = Bbh[r];     bl[j][0] = Bbl[r];
                bh[j][1] = Bbh[r + 4]; bl[j][1] = Bbl[r + 4];
            }
#pragma unroll
            for (int i = 0; i < 2; ++i)
#pragma unroll
                for (int j = 0; j < 4; ++j) {
                    mma8(acc[i][j][0], acc[i][j][1], acc[i][j][2], acc[i][j][3],
                         al[i][0], al[i][1], al[i][2], al[i][3], bh[j][0], bh[j][1]);
                    mma8(acc[i][j][0], acc[i][j][1], acc[i][j][2], acc[i][j][3],
                         ah[i][0], ah[i][1], ah[i][2], ah[i][3], bl[j][0], bl[j][1]);
                    mma8(acc[i][j][0], acc[i][j][1], acc[i][j][2], acc[i][j][3],
                         ah[i][0], ah[i][1], ah[i][2], ah[i][3], bh[j][0], bh[j][1]);
                }
        }
        __syncthreads();
        if (t + 1 < nt) {
            stage_store(Ah + (1 - c) * ABUF, Al + (1 - c) * ABUF,
                        Bh + (1 - c) * BBUF, Bl + (1 - c) * BBUF,
                        arow, akq, brow, bkq, ra0, ra1, rb0);
            __syncthreads();
        }
    }
}

__device__ void gemm_tile(float* __restrict__ C, int N, const float* __restrict__ bias,
                          const float* A0, const float* B0, int K0, int l0,
                          const float* A1, const float* B1, int K1, int l1,
                          int m0, int n0, int tid, uint32_t* sm_u) {
    uint32_t* Ah = sm_u;
    uint32_t* Bh = Ah + 2 * ABUF;
    uint32_t* Al = Bh + 2 * BBUF;
    uint32_t* Bl = Al + 2 * ABUF;
    float acc[2][4][4];
#pragma unroll
    for (int i = 0; i < 2; ++i)
#pragma unroll
        for (int j = 0; j < 4; ++j)
#pragma unroll
            for (int q = 0; q < 4; ++q) acc[i][j][q] = 0.f;

    gemm_part(A0, B0, K0, l0, m0, n0, tid, Ah, Al, Bh, Bl, acc);
    if (A1) gemm_part(A1, B1, K1, l1, m0, n0, tid, Ah, Al, Bh, Bl, acc);

    const int lane = tid & 31, warp = tid >> 5;
    const int wm = warp >> 1, wn = warp & 1, g = lane >> 2, tg = lane & 3;
#pragma unroll
    for (int i = 0; i < 2; ++i)
#pragma unroll
        for (int j = 0; j < 4; ++j) {
            int r = m0 + wm * 32 + i * 16 + g;
            int cc = n0 + wn * 32 + j * 8 + 2 * tg;
            float2 bb = make_float2(0.f, 0.f);
            if (bias) bb = *(const float2*)&bias[cc];
            *(float2*)&C[(size_t)r * N + cc] =
                make_float2(acc[i][j][0] + bb.x, acc[i][j][1] + bb.y);
            *(float2*)&C[(size_t)(r + 8) * N + cc] =
                make_float2(acc[i][j][2] + bb.x, acc[i][j][3] + bb.y);
        }
}

// =====================================================================
// MEGA KERNEL v4: identical to v3 except invert_pivot fully unrolled.
// =====================================================================
__global__ void __launch_bounds__(256, 2) mega_kernel(
    const float* __restrict__ u, const float* __restrict__ x0,
    const float* __restrict__ C1, const float* __restrict__ D11,
    const float* __restrict__ D12, const float* __restrict__ lam,
    const float* __restrict__ Fm, const float* __restrict__ B1,
    const float* __restrict__ B2, const float* __restrict__ E,
    const float* __restrict__ C2, const float* __restrict__ D22,
    float* __restrict__ yout) {
    extern __shared__ float smf[];
    __shared__ int s_tile;
    const int b = blockIdx.x;
    const int tid = threadIdx.x;
    int phase = 0;

    if (b >= BAT_BLOCKS) {
        // ================= GJ GROUP (120 blocks) =================
        const int g = b - BAT_BLOCKS;
        float* Ds = smf;
        float* RP = Ds + 64 * 65;
        float* Fs = RP + 64 * 65;
        float* rowbuf = Fs + 64 * 65;
        float* colbuf = rowbuf + 128;
        const int tr = tid >> 4, tc = tid & 15;

        // --- transposed init: WLU = [E^T | C2^T] ---
        {
            float* tsh = smf;
            const int tx = tid & 31, ty = tid >> 5;
            for (int tu = g; tu < 512; tu += GJ_BLOCKS) {
                const int R0 = (tu & 15) * 32;
                const int Cc0 = (tu >> 4) * 32;
                const float* src = (Cc0 < 512) ? (E + (size_t)Cc0 * 512 + R0)
                                               : (C2 + (size_t)(Cc0 - 512) * 512 + R0);
                __syncthreads();
#pragma unroll
                for (int i = 0; i < 32; i += 8)
                    tsh[(ty + i) * 33 + tx] = src[(size_t)(ty + i) * 512 + tx];
                __syncthreads();
#pragma unroll
                for (int i = 0; i < 32; i += 8)
                    g_WLU[(size_t)(R0 + ty + i) * 1024 + Cc0 + tx] = tsh[tx * 33 + ty + i];
            }
        }
        gbar(&g_bar_gj, GJ_BLOCKS, phase, tid);

        // --- 8 GJ steps, 1 barrier each ---
        for (int kb = 0; kb < 8; ++kb) {
            const int pc = kb * 64;
            const int ntiles = 15 - kb;
            const int tile = g >> 3, chunk = g & 7;
            const bool active = (tile < ntiles);

            if (active) {
                const int c0 = pc + 64 + tile * 64;
                invert_pivot(pc, tid, Ds, rowbuf, colbuf);

                for (int idx = tid; idx < 4096; idx += 256) {
                    int k = idx >> 6, c = idx & 63;
                    Fs[k * 65 + c] = g_WLU[(size_t)(pc + k) * 1024 + c0 + c];
                }
                __syncthreads();

                float rp[4][4] = {};
                for (int k = 0; k < 64; ++k) {
                    float w0 = Fs[k * 65 + tc * 4 + 0];
                    float w1 = Fs[k * 65 + tc * 4 + 1];
                    float w2 = Fs[k * 65 + tc * 4 + 2];
                    float w3 = Fs[k * 65 + tc * 4 + 3];
#pragma unroll
                    for (int i = 0; i < 4; ++i) {
                        float d = Ds[(tr * 4 + i) * 65 + k];
                        rp[i][0] += d * w0; rp[i][1] += d * w1;
                        rp[i][2] += d * w2; rp[i][3] += d * w3;
                    }
                }
                __syncthreads();
#pragma unroll
                for (int i = 0; i < 4; ++i)
#pragma unroll
                    for (int j = 0; j < 4; ++j)
                        RP[(tr * 4 + i) * 65 + tc * 4 + j] = rp[i][j];
                __syncthreads();

                if (chunk == kb) {
                    float* dst = &g_RPbuf[kb & 1][0];
                    for (int idx = tid; idx < 4096; idx += 256) {
                        int r = idx >> 6, c = idx & 63;
                        dst[(size_t)r * 1024 + c0 + c] = RP[r * 65 + c];
                    }
                } else {
                    const int r0 = chunk * 64;
                    const bool prev = (kb > 0) && (chunk == kb - 1);
                    const float* pbuf = &g_RPbuf[(kb + 1) & 1][0];
                    for (int idx = tid; idx < 4096; idx += 256) {
                        int r = idx >> 6, k = idx & 63;
                        Fs[r * 65 + k] = prev ? pbuf[(size_t)r * 1024 + pc + k]
                                              : g_WLU[(size_t)(r0 + r) * 1024 + pc + k];
                    }
                    __syncthreads();
                    float acc[4][4] = {};
                    for (int k = 0; k < 64; ++k) {
                        float w0 = RP[k * 65 + tc * 4 + 0];
                        float w1 = RP[k * 65 + tc * 4 + 1];
                        float w2 = RP[k * 65 + tc * 4 + 2];
                        float w3 = RP[k * 65 + tc * 4 + 3];
#pragma unroll
                        for (int i = 0; i < 4; ++i) {
                            float f = Fs[(tr * 4 + i) * 65 + k];
                            acc[i][0] += f * w0; acc[i][1] += f * w1;
                            acc[i][2] += f * w2; acc[i][3] += f * w3;
                        }
                    }
#pragma unroll
                    for (int i = 0; i < 4; ++i) {
                        const size_t off = (size_t)(r0 + tr * 4 + i) * 1024 + c0 + tc * 4;
                        float4 o = prev ? *(const float4*)&pbuf[(size_t)(tr * 4 + i) * 1024 + c0 + tc * 4]
                                        : *(const float4*)&g_WLU[off];
                        o.x -= acc[i][0]; o.y -= acc[i][1];
                        o.z -= acc[i][2]; o.w -= acc[i][3];
                        *(float4*)&g_WLU[off] = o;
                    }
                }
            }
            gbar(&g_bar_gj, GJ_BLOCKS, phase, tid);
        }

        // --- final commit of chunk-7 pivot rows (cols 512..1024) ---
        {
            const float* src = &g_RPbuf[1][0];
            for (int t = g * 256 + tid; t < 8192; t += GJ_BLOCKS * 256) {
                int r = t >> 7, c4 = (t & 127) * 4;
                *(float4*)&g_WLU[(size_t)(448 + r) * 1024 + 512 + c4] =
                    *(const float4*)&src[(size_t)r * 1024 + 512 + c4];
            }
        }
        gbar(&g_bar_gj, GJ_BLOCKS, phase, tid);

        // --- fold: W1 (32), W2 (64), ybias (2) = 98 units ---
        const float* G = &g_WLU[512];
        for (int fu = g; fu < 98; fu += GJ_BLOCKS) {
            if (fu < 32) {
                tn_tile(g_W1, G, 1024, B1, 256, nullptr, 256, 512,
                        (fu >> 2) * 64, (fu & 3) * 64, tid, smf);
            } else if (fu < 96) {
                int q = fu - 32;
                tn_tile(g_W2, G, 1024, B2, 512, D22, 512, 512,
                        (q >> 3) * 64, (q & 7) * 64, tid, smf);
            } else {
                wait_flag(&g_prep, tid);
                float* xs = smf;
                for (int i = tid; i < 512; i += 256) xs[i] = g_fx0[i];
                __syncthreads();
                int n = (fu - 96) * 256 + tid;
                float sv = 0.f;
#pragma unroll 8
                for (int t = 0; t < 512; ++t) sv += G[(size_t)t * 1024 + n] * xs[t];
                g_ybias[n] = sv;
                __syncthreads();
            }
        }
        gbar(&g_bar_gj, GJ_BLOCKS, phase, tid);
        if (g == 0 && tid == 0) {
            __threadfence();
            atomicExch((int*)&g_done, 1);
        }

        wait_flag(&g_recdone, tid);
    } else {
        // ================= BATCH GROUP (168 blocks) =================
        const int v = b;

        if (v < 67) {
            if (v < 64) {
                float* tsh = smf;
                const int bx = (v & 7) * 32, by = (v >> 3) * 32;
                const int tx = tid & 31, ty = tid >> 5;
#pragma unroll
                for (int i = 0; i < 32; i += 8)
                    tsh[(ty + i) * 33 + tx] = D11[(size_t)(by + ty + i) * 256 + bx + tx];
                __syncthreads();
#pragma unroll
                for (int i = 0; i < 32; i += 8)
                    g_D11T[(size_t)(bx + ty + i) * 256 + by + tx] = tsh[tx * 33 + ty + i];
            } else {
                const float4* xv = (const float4*)x0;
                if (v == 64) {
                    int n = tid;
                    const float4* r = (const float4*)(C1 + (size_t)n * DIN);
                    float s = 0.f;
                    for (int k = 0; k < DIN / 4; ++k) {
                        float4 a = r[k], bb = xv[k];
                        s += a.x * bb.x + a.y * bb.y + a.z * bb.z + a.w * bb.w;
                    }
                    g_c1x0[n] = s;
                } else {
                    int n = (v - 65) * 256 + tid;
                    const float4* r = (const float4*)(Fm + (size_t)n * DINT);
                    float s = 0.f;
                    for (int k = 0; k < DINT / 4; ++k) {
                        float4 a = r[k], bb = xv[k];
                        s += a.x * bb.x + a.y * bb.y + a.z * bb.z + a.w * bb.w;
                    }
                    g_fx0[n] = s;
                }
            }
        }
        gbar(&g_bar_bat, BAT_BLOCKS, phase, tid);
        if (v == 0 && tid == 0) {
            __threadfence();
            atomicExch((int*)&g_prep, 1);
        }

        if (v < 64) {
            gemm_tile(g_a, 256, g_c1x0,
                      u, D12, 512, 512,
                      nullptr, nullptr, 0, 0,
                      (v >> 2) * 128, (v & 3) * 64, tid, (uint32_t*)smf);
        }
        gbar(&g_bar_bat, BAT_BLOCKS, phase, tid);

        for (int ru = v; ru < 256; ru += BAT_BLOCKS) {
            const int lane = tid & 31;
            const int rb = ru * 8 + (tid >> 5);
            const float* arow = g_a + (size_t)rb * 256;
            float acc[8], linv[8], wv[8];
#pragma unroll
            for (int q = 0; q < 8; ++q) {
                acc[q] = arow[q * 32 + lane];
                linv[q] = 1.0f / lam[q * 32 + lane];
            }
#pragma unroll
            for (int q = 0; q < 8; ++q) {
#pragma unroll 8
                for (int t = 0; t < 32; ++t) {
                    int s = q * 32 + t;
                    float scaled = acc[q] * linv[q];
                    float vx = __shfl_sync(0xffffffffu, scaled, t);
                    float wt = tanhf(vx);
                    if (lane == t) wv[q] = wt;
                    const float* col = g_D11T + (size_t)s * 256;
                    if (lane > t) acc[q] += col[q * 32 + lane] * wt;
#pragma unroll
                    for (int q2 = q + 1; q2 < 8; ++q2)
                        acc[q2] += col[q2 * 32 + lane] * wt;
                }
            }
#pragma unroll
            for (int q = 0; q < 8; ++q)
                g_wm[(size_t)rb * 256 + q * 32 + lane] = wv[q];
        }
        gbar(&g_bar_bat, BAT_BLOCKS, phase, tid);
        if (v == 0 && tid == 0) {
            __threadfence();
            atomicExch((int*)&g_recdone, 1);
        }

        wait_flag(&g_done, tid);
    }

    // ============ shared y-GEMM work queue (all 288 blocks) ============
    for (;;) {
        __syncthreads();
        if (tid == 0) s_tile = atomicAdd(&g_yctr, 1);
        __syncthreads();
        const int t = s_tile;
        if (t >= 128) break;
        gemm_tile(yout, 512, g_ybias,
                  g_wm, g_W1, 256, 256,
                  u, g_W2, 512, 512,
                  (t >> 3) * 128, (t & 7) * 64, tid, (uint32_t*)smf);
    }
}

// ---------------- launch ----------------
extern "C" void kernel_launch(void* const* d_in, const int* in_sizes, int n_in,
                              void* d_out, int out_size) {
    const float *u, *x0, *C1, *D11, *D12, *lam, *Fm, *B1, *B2, *E, *C2, *D21, *D22;
    if (in_sizes[0] == BATCH * DIN) {
        u   = (const float*)d_in[0];  x0  = (const float*)d_in[1];
        C1  = (const float*)d_in[2];  D11 = (const float*)d_in[3];
        D12 = (const float*)d_in[4];  lam = (const float*)d_in[5];
        Fm  = (const float*)d_in[6];  B1  = (const float*)d_in[7];
        B2  = (const float*)d_in[8];  E   = (const float*)d_in[9];
        C2  = (const float*)d_in[10]; D21 = (const float*)d_in[11];
        D22 = (const float*)d_in[12];
    } else {
        C1  = (const float*)d_in[0];  D11 = (const float*)d_in[1];
        D12 = (const float*)d_in[2];  lam = (const float*)d_in[3];
        Fm  = (const float*)d_in[4];  B1  = (const float*)d_in[5];
        B2  = (const float*)d_in[6];  E   = (const float*)d_in[7];
        C2  = (const float*)d_in[8];  D21 = (const float*)d_in[9];
        D22 = (const float*)d_in[10]; u   = (const float*)d_in[11];
        x0  = (const float*)d_in[12];
    }
    (void)D21;  // identically zero by construction

    cudaFuncSetAttribute(mega_kernel,
                         cudaFuncAttributeMaxDynamicSharedMemorySize, GEMM_SMEM);

    reset_kernel<<<1, 32>>>();
    mega_kernel<<<TOT_BLOCKS, 256, GEMM_SMEM>>>(
        u, x0, C1, D11, D12, lam, Fm, B1, B2, E, C2, D22, (float*)d_out);
}

// round 14
// speedup vs baseline: 1.9522x; 1.0653x over previous
#include <cuda_runtime.h>
#include <math.h>
#include <stdint.h>

#define BATCH 2048
#define DIN   512
#define DOUT  512
#define DINT  512
#define DNL   256

#define BAT_BLOCKS  168
#define GJ_BLOCKS   120
#define TOT_BLOCKS  288

// ---------------- device scratch ----------------
__device__ __align__(16) float g_WLU[512 * 1024];
__device__ __align__(16) float g_RPbuf[2][64 * 1024];  // deferred pivot-row commits
__device__ __align__(16) float g_Dinvg[2][64 * 64];    // double-buffered pivot inverse
__device__ __align__(16) float g_a[BATCH * DNL];
__device__ __align__(16) float g_wm[BATCH * DNL];
__device__ __align__(16) float g_D11T[DNL * DNL];
__device__ __align__(16) float g_W1[DOUT * DNL];
__device__ __align__(16) float g_W2[DOUT * DIN];
__device__ __align__(16) float g_c1x0[DNL];
__device__ __align__(16) float g_fx0[DINT];
__device__ __align__(16) float g_ybias[DOUT];
__device__ volatile int g_bar_gj;
__device__ volatile int g_bar_bat;
__device__ volatile int g_done;
__device__ volatile int g_prep;
__device__ volatile int g_recdone;
__device__ volatile int g_dgen;   // highest step whose Dinv is published
__device__ int g_yctr;

__global__ void reset_kernel() {
    g_bar_gj = 0; g_bar_bat = 0; g_done = 0; g_prep = 0; g_recdone = 0;
    g_yctr = 0; g_dgen = -1;
}

// ---------------- group barrier ----------------
__device__ __forceinline__ void gbar(volatile int* ctr, int nblocks, int& phase, int tid) {
    __syncthreads();
    ++phase;
    if (tid == 0) {
        __threadfence();
        atomicAdd((int*)ctr, 1);
        const int target = nblocks * phase;
        while (*ctr < target) __nanosleep(128);
        __threadfence();
    }
    __syncthreads();
}

__device__ __forceinline__ void wait_flag(volatile int* flag, int tid) {
    if (tid == 0) {
        while (*flag == 0) __nanosleep(128);
    }
    __syncthreads();
    __threadfence();
}

// ---------------- fully-unrolled 64x64 GJ inversion core ----------------
// v[4][8]: thread (rg=tid>>4, cg=tid&15) owns rows rg*4+i, cols cg*8+j of [P|I].
// Result (right half) written to outg[r*64 + c].
__device__ __forceinline__ void gj_inv_core(int tid, float v[4][8],
                                            float* rowbuf, float* colbuf,
                                            float* __restrict__ outg) {
    const int rg = tid >> 4, cg = tid & 15;
#pragma unroll 64
    for (int jj = 0; jj < 64; ++jj) {
        const int pr = jj >> 2, sub = jj & 3;
        const int pcg = jj >> 3, subc = jj & 7;
        if (rg == pr) {
#pragma unroll
            for (int q = 0; q < 8; ++q) rowbuf[cg * 8 + q] = v[sub][q];
        }
        if (cg == pcg) {
#pragma unroll
            for (int i = 0; i < 4; ++i) colbuf[rg * 4 + i] = v[i][subc];
        }
        __syncthreads();
        const float pinv = 1.0f / rowbuf[jj];
        float f[4];
#pragma unroll
        for (int i = 0; i < 4; ++i) f[i] = colbuf[rg * 4 + i] * pinv;
        float rv[8];
#pragma unroll
        for (int q = 0; q < 8; ++q) rv[q] = rowbuf[cg * 8 + q];
        if (rg == pr) {
#pragma unroll
            for (int q = 0; q < 8; ++q) v[sub][q] = rv[q] * pinv;
        }
#pragma unroll
        for (int i = 0; i < 4; ++i) {
            if (rg == pr && i == sub) continue;
#pragma unroll
            for (int q = 0; q < 8; ++q) v[i][q] -= f[i] * rv[q];
        }
        __syncthreads();
    }
    const int rgl = tid >> 4, cgl = tid & 15;
#pragma unroll
    for (int i = 0; i < 4; ++i) {
        int r = rgl * 4 + i;
#pragma unroll
        for (int j = 0; j < 8; ++j) {
            int c = cgl * 8 + j;
            if (c >= 64) outg[r * 64 + (c - 64)] = v[i][j];
        }
    }
    __syncthreads();
}

// loader: from global (g_WLU pivot block at pc)
__device__ __forceinline__ void invert_from_gwlu(int pc, int tid,
                                                 float* rowbuf, float* colbuf,
                                                 float* outg) {
    const int rg = tid >> 4, cg = tid & 15;
    float v[4][8];
#pragma unroll
    for (int i = 0; i < 4; ++i) {
        int r = rg * 4 + i;
#pragma unroll
        for (int j = 0; j < 8; ++j) {
            int c = cg * 8 + j;
            v[i][j] = (c < 64) ? g_WLU[(size_t)(pc + r) * 1024 + pc + c]
                               : ((c - 64) == r ? 1.f : 0.f);
        }
    }
    gj_inv_core(tid, v, rowbuf, colbuf, outg);
}

// loader: from shared tile (stride 65)
__device__ __forceinline__ void invert_from_sh(const float* Ts, int tid,
                                               float* rowbuf, float* colbuf,
                                               float* outg) {
    const int rg = tid >> 4, cg = tid & 15;
    float v[4][8];
#pragma unroll
    for (int i = 0; i < 4; ++i) {
        int r = rg * 4 + i;
#pragma unroll
        for (int j = 0; j < 8; ++j) {
            int c = cg * 8 + j;
            v[i][j] = (c < 64) ? Ts[r * 65 + c] : ((c - 64) == r ? 1.f : 0.f);
        }
    }
    gj_inv_core(tid, v, rowbuf, colbuf, outg);
}

// ---------------- TN tile ----------------
__device__ void tn_tile(float* __restrict__ C,
                        const float* __restrict__ A, int lda,
                        const float* __restrict__ B, int ldb,
                        const float* __restrict__ Add, int N, int K,
                        int m0, int n0, int tid, float* smem) {
    float* As = smem;
    float* Bs = smem + 16 * 68;
    const int tr = tid >> 4, tc = tid & 15;
    float acc[4][4] = {};
    for (int t0 = 0; t0 < K; t0 += 16) {
        __syncthreads();
        for (int idx = tid; idx < 1024; idx += 256) {
            int t = idx >> 6, m = idx & 63;
            As[t * 68 + m] = A[(size_t)(t0 + t) * lda + m0 + m];
            Bs[t * 68 + m] = B[(size_t)(t0 + t) * ldb + n0 + m];
        }
        __syncthreads();
#pragma unroll
        for (int t = 0; t < 16; ++t) {
            float a[4], bv[4];
#pragma unroll
            for (int i = 0; i < 4; ++i) a[i] = As[t * 68 + tr * 4 + i];
#pragma unroll
            for (int j = 0; j < 4; ++j) bv[j] = Bs[t * 68 + tc * 4 + j];
#pragma unroll
            for (int i = 0; i < 4; ++i)
#pragma unroll
                for (int j = 0; j < 4; ++j) acc[i][j] += a[i] * bv[j];
        }
    }
    __syncthreads();
#pragma unroll
    for (int i = 0; i < 4; ++i) {
        int r = m0 + tr * 4 + i;
#pragma unroll
        for (int j = 0; j < 4; ++j) {
            float v = acc[i][j];
            if (Add) v += Add[(size_t)r * N + n0 + tc * 4 + j];
            C[(size_t)r * N + n0 + tc * 4 + j] = v;
        }
    }
}

// ---------------- 3xTF32 MMA GEMM machinery ----------------
__device__ __forceinline__ uint32_t f2tf(float f) {
    uint32_t u;
    asm("cvt.rna.tf32.f32 %0, %1;" : "=r"(u) : "f"(f));
    return u;
}
__device__ __forceinline__ void mma8(float& c0, float& c1, float& c2, float& c3,
                                     uint32_t a0, uint32_t a1, uint32_t a2, uint32_t a3,
                                     uint32_t b0, uint32_t b1) {
    asm volatile(
        "mma.sync.aligned.m16n8k8.row.col.f32.tf32.tf32.f32 "
        "{%0,%1,%2,%3},{%4,%5,%6,%7},{%8,%9},{%0,%1,%2,%3};"
        : "+f"(c0), "+f"(c1), "+f"(c2), "+f"(c3)
        : "r"(a0), "r"(a1), "r"(a2), "r"(a3), "r"(b0), "r"(b1));
}

#define ASTRIDE 20
#define ABUF (128 * ASTRIDE)
#define BBUF (64 * ASTRIDE)
#define GEMM_SMEM ((2 * ABUF + 2 * BBUF) * 8)  // 61440 bytes

__device__ __forceinline__ void stage_store(uint32_t* Ah, uint32_t* Al,
                                            uint32_t* Bh, uint32_t* Bl,
                                            int arow, int akq, int brow, int bkq,
                                            float4 ra0, float4 ra1, float4 rb0) {
    uint32_t* ah = Ah + arow * ASTRIDE + akq;
    uint32_t* al = Al + arow * ASTRIDE + akq;
    float av[8] = {ra0.x, ra0.y, ra0.z, ra0.w, ra1.x, ra1.y, ra1.z, ra1.w};
#pragma unroll
    for (int j = 0; j < 8; ++j) {
        uint32_t h = f2tf(av[j]);
        ah[j] = h;
        al[j] = f2tf(av[j] - __uint_as_float(h));
    }
    uint32_t* bh = Bh + brow * ASTRIDE + bkq;
    uint32_t* bl = Bl + brow * ASTRIDE + bkq;
    float bv[4] = {rb0.x, rb0.y, rb0.z, rb0.w};
#pragma unroll
    for (int j = 0; j < 4; ++j) {
        uint32_t h = f2tf(bv[j]);
        bh[j] = h;
        bl[j] = f2tf(bv[j] - __uint_as_float(h));
    }
}

__device__ void gemm_part(const float* __restrict__ A,
                          const float* __restrict__ Bm,
                          int K, int ldb, int m0, int n0, int tid,
                          uint32_t* Ah, uint32_t* Al,
                          uint32_t* Bh, uint32_t* Bl,
                          float (&acc)[2][4][4]) {
    const int arow = tid >> 1, akq = (tid & 1) * 8;
    const int brow = tid >> 2, bkq = (tid & 3) * 4;
    const int lane = tid & 31, warp = tid >> 5;
    const int wm = warp >> 1, wn = warp & 1, g = lane >> 2, tg = lane & 3;
    const int nt = K >> 4;
    float4 ra0, ra1, rb0;
    {
        const float* ap = A + (size_t)(m0 + arow) * K + akq;
        ra0 = *(const float4*)ap;
        ra1 = *(const float4*)(ap + 4);
        const float* bp = Bm + (size_t)(n0 + brow) * ldb + bkq;
        rb0 = *(const float4*)bp;
    }
    __syncthreads();
    stage_store(Ah, Al, Bh, Bl, arow, akq, brow, bkq, ra0, ra1, rb0);
    __syncthreads();
    for (int t = 0; t < nt; ++t) {
        const int c = t & 1;
        if (t + 1 < nt) {
            const float* ap = A + (size_t)(m0 + arow) * K + (t + 1) * 16 + akq;
            ra0 = *(const float4*)ap;
            ra1 = *(const float4*)(ap + 4);
            const float* bp = Bm + (size_t)(n0 + brow) * ldb + (t + 1) * 16 + bkq;
            rb0 = *(const float4*)bp;
        }
        const uint32_t* Abh = Ah + c * ABUF;
        const uint32_t* Abl = Al + c * ABUF;
        const uint32_t* Bbh = Bh + c * BBUF;
        const uint32_t* Bbl = Bl + c * BBUF;
#pragma unroll
        for (int ks = 0; ks < 16; ks += 8) {
            uint32_t ah[2][4], al[2][4], bh[4][2], bl[4][2];
#pragma unroll
            for (int i = 0; i < 2; ++i) {
                int r = (wm * 32 + i * 16 + g) * ASTRIDE + ks + tg;
                ah[i][0] = Abh[r];                   al[i][0] = Abl[r];
                ah[i][1] = Abh[r + 8 * ASTRIDE];     al[i][1] = Abl[r + 8 * ASTRIDE];
                ah[i][2] = Abh[r + 4];               al[i][2] = Abl[r + 4];
                ah[i][3] = Abh[r + 8 * ASTRIDE + 4]; al[i][3] = Abl[r + 8 * ASTRIDE + 4];
            }
#pragma unroll
            for (int j = 0; j < 4; ++j) {
                int r = (wn * 32 + j * 8 + g) * ASTRIDE + ks + tg;
                bh[j][0] = Bbh[r];     bl[j][0] = Bbl[r];
                bh[j][1] = Bbh[r + 4]; bl[j][1] = Bbl[r + 4];
            }
#pragma unroll
            for (int i = 0; i < 2; ++i)
#pragma unroll
                for (int j = 0; j < 4; ++j) {
                    mma8(acc[i][j][0], acc[i][j][1], acc[i][j][2], acc[i][j][3],
                         al[i][0], al[i][1], al[i][2], al[i][3], bh[j][0], bh[j][1]);
                    mma8(acc[i][j][0], acc[i][j][1], acc[i][j][2], acc[i][j][3],
                         ah[i][0], ah[i][1], ah[i][2], ah[i][3], bl[j][0], bl[j][1]);
                    mma8(acc[i][j][0], acc[i][j][1], acc[i][j][2], acc[i][j][3],
                         ah[i][0], ah[i][1], ah[i][2], ah[i][3], bh[j][0], bh[j][1]);
                }
        }
        __syncthreads();
        if (t + 1 < nt) {
            stage_store(Ah + (1 - c) * ABUF, Al + (1 - c) * ABUF,
                        Bh + (1 - c) * BBUF, Bl + (1 - c) * BBUF,
                        arow, akq, brow, bkq, ra0, ra1, rb0);
            __syncthreads();
        }
    }
}

__device__ void gemm_tile(float* __restrict__ C, int N, const float* __restrict__ bias,
                          const float* A0, const float* B0, int K0, int l0,
                          const float* A1, const float* B1, int K1, int l1,
                          int m0, int n0, int tid, uint32_t* sm_u) {
    uint32_t* Ah = sm_u;
    uint32_t* Bh = Ah + 2 * ABUF;
    uint32_t* Al = Bh + 2 * BBUF;
    uint32_t* Bl = Al + 2 * ABUF;
    float acc[2][4][4];
#pragma unroll
    for (int i = 0; i < 2; ++i)
#pragma unroll
        for (int j = 0; j < 4; ++j)
#pragma unroll
            for (int q = 0; q < 4; ++q) acc[i][j][q] = 0.f;

    gemm_part(A0, B0, K0, l0, m0, n0, tid, Ah, Al, Bh, Bl, acc);
    if (A1) gemm_part(A1, B1, K1, l1, m0, n0, tid, Ah, Al, Bh, Bl, acc);

    const int lane = tid & 31, warp = tid >> 5;
    const int wm = warp >> 1, wn = warp & 1, g = lane >> 2, tg = lane & 3;
#pragma unroll
    for (int i = 0; i < 2; ++i)
#pragma unroll
        for (int j = 0; j < 4; ++j) {
            int r = m0 + wm * 32 + i * 16 + g;
            int cc = n0 + wn * 32 + j * 8 + 2 * tg;
            float2 bb = make_float2(0.f, 0.f);
            if (bias) bb = *(const float2*)&bias[cc];
            *(float2*)&C[(size_t)r * N + cc] =
                make_float2(acc[i][j][0] + bb.x, acc[i][j][1] + bb.y);
            *(float2*)&C[(size_t)(r + 8) * N + cc] =
                make_float2(acc[i][j][2] + bb.x, acc[i][j][3] + bb.y);
        }
}

// =====================================================================
// MEGA KERNEL v5: designated-inverter pipelined GJ
// =====================================================================
__global__ void __launch_bounds__(256, 2) mega_kernel(
    const float* __restrict__ u, const float* __restrict__ x0,
    const float* __restrict__ C1, const float* __restrict__ D11,
    const float* __restrict__ D12, const float* __restrict__ lam,
    const float* __restrict__ Fm, const float* __restrict__ B1,
    const float* __restrict__ B2, const float* __restrict__ E,
    const float* __restrict__ C2, const float* __restrict__ D22,
    float* __restrict__ yout) {
    extern __shared__ float smf[];
    __shared__ int s_tile;
    const int b = blockIdx.x;
    const int tid = threadIdx.x;
    int phase = 0;

    if (b >= BAT_BLOCKS) {
        // ================= GJ GROUP (120 blocks) =================
        const int g = b - BAT_BLOCKS;
        float* Ds = smf;                  // 64x65 (Dinv)
        float* RP = Ds + 64 * 65;
        float* Fs = RP + 64 * 65;
        float* rowbuf = Fs + 64 * 65;
        float* colbuf = rowbuf + 128;
        const int tr = tid >> 4, tc = tid & 15;

        // --- transposed init: WLU = [E^T | C2^T] ---
        {
            float* tsh = smf;
            const int tx = tid & 31, ty = tid >> 5;
            for (int tu = g; tu < 512; tu += GJ_BLOCKS) {
                const int R0 = (tu & 15) * 32;
                const int Cc0 = (tu >> 4) * 32;
                const float* src = (Cc0 < 512) ? (E + (size_t)Cc0 * 512 + R0)
                                               : (C2 + (size_t)(Cc0 - 512) * 512 + R0);
                __syncthreads();
#pragma unroll
                for (int i = 0; i < 32; i += 8)
                    tsh[(ty + i) * 33 + tx] = src[(size_t)(ty + i) * 512 + tx];
                __syncthreads();
#pragma unroll
                for (int i = 0; i < 32; i += 8)
                    g_WLU[(size_t)(R0 + ty + i) * 1024 + Cc0 + tx] = tsh[tx * 33 + ty + i];
            }
        }
        gbar(&g_bar_gj, GJ_BLOCKS, phase, tid);

        // --- bootstrap: block 0 inverts pivot(0), publishes ---
        if (g == 0) {
            invert_from_gwlu(0, tid, rowbuf, colbuf, &g_Dinvg[0][0]);
            __threadfence();
            if (tid == 0) g_dgen = 0;
        }

        // --- 8 GJ steps, 1 barrier each; Dinv(kb+1) published by designee ---
        for (int kb = 0; kb < 8; ++kb) {
            const int pc = kb * 64;
            const int ntiles = 15 - kb;
            const int tile = g >> 3, chunk = g & 7;
            const bool active = (tile < ntiles);
            const bool desig = (tile == 0) && (chunk == kb + 1) && (kb < 7);

            if (active) {
                // wait + load Dinv(kb)
                if (tid == 0) {
                    while (g_dgen < kb) __nanosleep(64);
                }
                __syncthreads();
                __threadfence();
                const float* dsrc = &g_Dinvg[kb & 1][0];
                for (int idx = tid; idx < 4096; idx += 256)
                    Ds[(idx >> 6) * 65 + (idx & 63)] = dsrc[idx];

                const int c0 = pc + 64 + tile * 64;
                // Wk = W[pivot rows kb][tile] -> Fs
                for (int idx = tid; idx < 4096; idx += 256) {
                    int k = idx >> 6, c = idx & 63;
                    Fs[k * 65 + c] = g_WLU[(size_t)(pc + k) * 1024 + c0 + c];
                }
                __syncthreads();

                // RP = Dinv @ Wk
                float rp[4][4] = {};
                for (int k = 0; k < 64; ++k) {
                    float w0 = Fs[k * 65 + tc * 4 + 0];
                    float w1 = Fs[k * 65 + tc * 4 + 1];
                    float w2 = Fs[k * 65 + tc * 4 + 2];
                    float w3 = Fs[k * 65 + tc * 4 + 3];
#pragma unroll
                    for (int i = 0; i < 4; ++i) {
                        float d = Ds[(tr * 4 + i) * 65 + k];
                        rp[i][0] += d * w0; rp[i][1] += d * w1;
                        rp[i][2] += d * w2; rp[i][3] += d * w3;
                    }
                }
                __syncthreads();
#pragma unroll
                for (int i = 0; i < 4; ++i)
#pragma unroll
                    for (int j = 0; j < 4; ++j)
                        RP[(tr * 4 + i) * 65 + tc * 4 + j] = rp[i][j];
                __syncthreads();

                if (chunk == kb) {
                    float* dst = &g_RPbuf[kb & 1][0];
                    for (int idx = tid; idx < 4096; idx += 256) {
                        int r = idx >> 6, c = idx & 63;
                        dst[(size_t)r * 1024 + c0 + c] = RP[r * 65 + c];
                    }
                } else {
                    const int r0 = chunk * 64;
                    const bool prev = (kb > 0) && (chunk == kb - 1);
                    const float* pbuf = &g_RPbuf[(kb + 1) & 1][0];
                    for (int idx = tid; idx < 4096; idx += 256) {
                        int r = idx >> 6, k = idx & 63;
                        Fs[r * 65 + k] = prev ? pbuf[(size_t)r * 1024 + pc + k]
                                              : g_WLU[(size_t)(r0 + r) * 1024 + pc + k];
                    }
                    __syncthreads();
                    float acc[4][4] = {};
                    for (int k = 0; k < 64; ++k) {
                        float w0 = RP[k * 65 + tc * 4 + 0];
                        float w1 = RP[k * 65 + tc * 4 + 1];
                        float w2 = RP[k * 65 + tc * 4 + 2];
                        float w3 = RP[k * 65 + tc * 4 + 3];
#pragma unroll
                        for (int i = 0; i < 4; ++i) {
                            float f = Fs[(tr * 4 + i) * 65 + k];
                            acc[i][0] += f * w0; acc[i][1] += f * w1;
                            acc[i][2] += f * w2; acc[i][3] += f * w3;
                        }
                    }
                    float nv[4][4];
#pragma unroll
                    for (int i = 0; i < 4; ++i) {
                        const size_t off = (size_t)(r0 + tr * 4 + i) * 1024 + c0 + tc * 4;
                        float4 o = prev ? *(const float4*)&pbuf[(size_t)(tr * 4 + i) * 1024 + c0 + tc * 4]
                                        : *(const float4*)&g_WLU[off];
                        o.x -= acc[i][0]; o.y -= acc[i][1];
                        o.z -= acc[i][2]; o.w -= acc[i][3];
                        nv[i][0] = o.x; nv[i][1] = o.y; nv[i][2] = o.z; nv[i][3] = o.w;
                        *(float4*)&g_WLU[off] = o;
                    }
                    if (desig) {
                        // my updated tile IS pivot(kb+1): invert & publish
                        __syncthreads();  // all F reads of Fs done
#pragma unroll
                        for (int i = 0; i < 4; ++i)
#pragma unroll
                            for (int j = 0; j < 4; ++j)
                                Fs[(tr * 4 + i) * 65 + tc * 4 + j] = nv[i][j];
                        __syncthreads();
                        invert_from_sh(Fs, tid, rowbuf, colbuf,
                                       &g_Dinvg[(kb + 1) & 1][0]);
                        __threadfence();
                        if (tid == 0) g_dgen = kb + 1;
                    }
                }
            }
            gbar(&g_bar_gj, GJ_BLOCKS, phase, tid);
        }

        // --- final commit of chunk-7 pivot rows (cols 512..1024) ---
        {
            const float* src = &g_RPbuf[1][0];
            for (int t = g * 256 + tid; t < 8192; t += GJ_BLOCKS * 256) {
                int r = t >> 7, c4 = (t & 127) * 4;
                *(float4*)&g_WLU[(size_t)(448 + r) * 1024 + 512 + c4] =
                    *(const float4*)&src[(size_t)r * 1024 + 512 + c4];
            }
        }
        gbar(&g_bar_gj, GJ_BLOCKS, phase, tid);

        // --- fold: W1 (32), W2 (64), ybias (2) = 98 units ---
        const float* G = &g_WLU[512];
        for (int fu = g; fu < 98; fu += GJ_BLOCKS) {
            if (fu < 32) {
                tn_tile(g_W1, G, 1024, B1, 256, nullptr, 256, 512,
                        (fu >> 2) * 64, (fu & 3) * 64, tid, smf);
            } else if (fu < 96) {
                int q = fu - 32;
                tn_tile(g_W2, G, 1024, B2, 512, D22, 512, 512,
                        (q >> 3) * 64, (q & 7) * 64, tid, smf);
            } else {
                wait_flag(&g_prep, tid);
                float* xs = smf;
                for (int i = tid; i < 512; i += 256) xs[i] = g_fx0[i];
                __syncthreads();
                int n = (fu - 96) * 256 + tid;
                float sv = 0.f;
#pragma unroll 8
                for (int t = 0; t < 512; ++t) sv += G[(size_t)t * 1024 + n] * xs[t];
                g_ybias[n] = sv;
                __syncthreads();
            }
        }
        gbar(&g_bar_gj, GJ_BLOCKS, phase, tid);
        if (g == 0 && tid == 0) {
            __threadfence();
            atomicExch((int*)&g_done, 1);
        }

        wait_flag(&g_recdone, tid);
    } else {
        // ================= BATCH GROUP (168 blocks) =================
        const int v = b;

        if (v < 67) {
            if (v < 64) {
                float* tsh = smf;
                const int bx = (v & 7) * 32, by = (v >> 3) * 32;
                const int tx = tid & 31, ty = tid >> 5;
#pragma unroll
                for (int i = 0; i < 32; i += 8)
                    tsh[(ty + i) * 33 + tx] = D11[(size_t)(by + ty + i) * 256 + bx + tx];
                __syncthreads();
#pragma unroll
                for (int i = 0; i < 32; i += 8)
                    g_D11T[(size_t)(bx + ty + i) * 256 + by + tx] = tsh[tx * 33 + ty + i];
            } else {
                const float4* xv = (const float4*)x0;
                if (v == 64) {
                    int n = tid;
                    const float4* r = (const float4*)(C1 + (size_t)n * DIN);
                    float s = 0.f;
                    for (int k = 0; k < DIN / 4; ++k) {
                        float4 a = r[k], bb = xv[k];
                        s += a.x * bb.x + a.y * bb.y + a.z * bb.z + a.w * bb.w;
                    }
                    g_c1x0[n] = s;
                } else {
                    int n = (v - 65) * 256 + tid;
                    const float4* r = (const float4*)(Fm + (size_t)n * DINT);
                    float s = 0.f;
                    for (int k = 0; k < DINT / 4; ++k) {
                        float4 a = r[k], bb = xv[k];
                        s += a.x * bb.x + a.y * bb.y + a.z * bb.z + a.w * bb.w;
                    }
                    g_fx0[n] = s;
                }
            }
        }
        gbar(&g_bar_bat, BAT_BLOCKS, phase, tid);
        if (v == 0 && tid == 0) {
            __threadfence();
            atomicExch((int*)&g_prep, 1);
        }

        if (v < 64) {
            gemm_tile(g_a, 256, g_c1x0,
                      u, D12, 512, 512,
                      nullptr, nullptr, 0, 0,
                      (v >> 2) * 128, (v & 3) * 64, tid, (uint32_t*)smf);
        }
        gbar(&g_bar_bat, BAT_BLOCKS, phase, tid);

        for (int ru = v; ru < 256; ru += BAT_BLOCKS) {
            const int lane = tid & 31;
            const int rb = ru * 8 + (tid >> 5);
            const float* arow = g_a + (size_t)rb * 256;
            float acc[8], linv[8], wv[8];
#pragma unroll
            for (int q = 0; q < 8; ++q) {
                acc[q] = arow[q * 32 + lane];
                linv[q] = 1.0f / lam[q * 32 + lane];
            }
#pragma unroll
            for (int q = 0; q < 8; ++q) {
#pragma unroll 8
                for (int t = 0; t < 32; ++t) {
                    int s = q * 32 + t;
                    float scaled = acc[q] * linv[q];
                    float vx = __shfl_sync(0xffffffffu, scaled, t);
                    float wt = tanhf(vx);
                    if (lane == t) wv[q] = wt;
                    const float* col = g_D11T + (size_t)s * 256;
                    if (lane > t) acc[q] += col[q * 32 + lane] * wt;
#pragma unroll
                    for (int q2 = q + 1; q2 < 8; ++q2)
                        acc[q2] += col[q2 * 32 + lane] * wt;
                }
            }
#pragma unroll
            for (int q = 0; q < 8; ++q)
                g_wm[(size_t)rb * 256 + q * 32 + lane] = wv[q];
        }
        gbar(&g_bar_bat, BAT_BLOCKS, phase, tid);
        if (v == 0 && tid == 0) {
            __threadfence();
            atomicExch((int*)&g_recdone, 1);
        }

        wait_flag(&g_done, tid);
    }

    // ============ shared y-GEMM work queue (all 288 blocks) ============
    for (;;) {
        __syncthreads();
        if (tid == 0) s_tile = atomicAdd(&g_yctr, 1);
        __syncthreads();
        const int t = s_tile;
        if (t >= 128) break;
        gemm_tile(yout, 512, g_ybias,
                  g_wm, g_W1, 256, 256,
                  u, g_W2, 512, 512,
                  (t >> 3) * 128, (t & 7) * 64, tid, (uint32_t*)smf);
    }
}

// ---------------- launch ----------------
extern "C" void kernel_launch(void* const* d_in, const int* in_sizes, int n_in,
                              void* d_out, int out_size) {
    const float *u, *x0, *C1, *D11, *D12, *lam, *Fm, *B1, *B2, *E, *C2, *D21, *D22;
    if (in_sizes[0] == BATCH * DIN) {
        u   = (const float*)d_in[0];  x0  = (const float*)d_in[1];
        C1  = (const float*)d_in[2];  D11 = (const float*)d_in[3];
        D12 = (const float*)d_in[4];  lam = (const float*)d_in[5];
        Fm  = (const float*)d_in[6];  B1  = (const float*)d_in[7];
        B2  = (const float*)d_in[8];  E   = (const float*)d_in[9];
        C2  = (const float*)d_in[10]; D21 = (const float*)d_in[11];
        D22 = (const float*)d_in[12];
    } else {
        C1  = (const float*)d_in[0];  D11 = (const float*)d_in[1];
        D12 = (const float*)d_in[2];  lam = (const float*)d_in[3];
        Fm  = (const float*)d_in[4];  B1  = (const float*)d_in[5];
        B2  = (const float*)d_in[6];  E   = (const float*)d_in[7];
        C2  = (const float*)d_in[8];  D21 = (const float*)d_in[9];
        D22 = (const float*)d_in[10]; u   = (const float*)d_in[11];
        x0  = (const float*)d_in[12];
    }
    (void)D21;  // identically zero by construction

    cudaFuncSetAttribute(mega_kernel,
                         cudaFuncAttributeMaxDynamicSharedMemorySize, GEMM_SMEM);

    reset_kernel<<<1, 32>>>();
    mega_kernel<<<TOT_BLOCKS, 256, GEMM_SMEM>>>(
        u, x0, C1, D11, D12, lam, Fm, B1, B2, E, C2, D22, (float*)d_out);
}